// round 13
// baseline (speedup 1.0000x reference)
#include <cuda_runtime.h>
#include <cuda_fp16.h>
#include <math.h>
#include <stdint.h>

// Problem constants
// N=16, C=128, T=128, V=25, K=3, H=8, OC=256, C/H=16, OC/H=32
// x: (16,128,128,25)  out: (16,256,128,25)

#define TV 3200          // T*V
#define CTV 409600       // C*T*V

// ---- scratch (device globals; allocation-free) ----
__device__ float d_BnA[24 * 625];
__device__ float d_bsum[256];
__device__ __align__(16) __half d_res_preh[16 * 256 * 3200];   // [n][ch][t][w]
__device__ __align__(16) __half d_out_preh[16 * 256 * 3200];   // [n][ch][t][w]
__device__ __align__(16) __half d_G2h[8 * 896 * 400];   // fused weights, k'=v*16+c
__device__ __align__(16) __half d_xth[16 * 3200 * 128];    // x: [n][t*25+v][h*16+c]
__device__ __align__(16) __half d_rwh[256 * 128];          // res_w fp16
__device__ float d_ss[1024];
__device__ float d_rpart[800 * 256];             // res-path BN partials
__device__ float d_mpart[8 * 7 * 16 * 128 * 2];  // main-path BN partials

__device__ __forceinline__ void mma_f16(float c[4], const uint32_t a[4],
                                        const uint32_t b[2]) {
    asm volatile(
        "mma.sync.aligned.m16n8k16.row.col.f32.f16.f16.f32 "
        "{%0,%1,%2,%3},{%4,%5,%6,%7},{%8,%9},{%0,%1,%2,%3};"
        : "+f"(c[0]), "+f"(c[1]), "+f"(c[2]), "+f"(c[3])
        : "r"(a[0]), "r"(a[1]), "r"(a[2]), "r"(a[3]), "r"(b[0]), "r"(b[1]));
}
__device__ __forceinline__ uint32_t s2u(const void* p) {
    return (uint32_t)__cvta_generic_to_shared(p);
}
#define LDSM4(r0, r1, r2, r3, addr)                                        \
    asm volatile("ldmatrix.sync.aligned.m8n8.x4.shared.b16 {%0,%1,%2,%3},[%4];" \
                 : "=r"(r0), "=r"(r1), "=r"(r2), "=r"(r3) : "r"(addr))
__device__ __forceinline__ void cp16(uint32_t dst, const void* src) {
    asm volatile("cp.async.cg.shared.global [%0], [%1], 16;"
                 :: "r"(dst), "l"(src));
}
#define CP_COMMIT() asm volatile("cp.async.commit_group;" ::: "memory")
#define CP_WAIT(n)  asm volatile("cp.async.wait_group %0;" :: "n"(n) : "memory")

// ---------------------------------------------------------------------------
// Kernel 1: build BnA and summed bias.
// ---------------------------------------------------------------------------
__global__ void prep_kernel(const int* __restrict__ hop,
                            const float* __restrict__ emb,
                            const float* __restrict__ A,
                            const float* __restrict__ b_block) {
    int g = blockIdx.x;
    int w = threadIdx.x;
    if (g < 24) {
        if (w < 25) {
            const float* eg = emb + g * 12;
            const float* Ag = A + g * 625;
            float sb = 0.f, sa = 0.f;
            for (int v = 0; v < 25; ++v) {
                float bv = eg[hop[v * 25 + w]];
                float av = Ag[v * 25 + w];
                sb += bv * bv;
                sa += av * av;
            }
            float rb = 1.f / (sqrtf(sb) + 1e-4f);
            float ra = 1.f / (sqrtf(sa) + 1e-4f);
            for (int v = 0; v < 25; ++v) {
                float bv = eg[hop[v * 25 + w]];
                float av = Ag[v * 25 + w];
                d_BnA[g * 625 + v * 25 + w] = bv * rb + av * ra;
            }
        }
    } else {
        for (int oc = w; oc < 256; oc += 32)
            d_bsum[oc] = b_block[oc] + b_block[256 + oc] + b_block[512 + oc];
    }
}

// ---------------------------------------------------------------------------
// Kernel 1a: convert res_w -> fp16.
// ---------------------------------------------------------------------------
__global__ __launch_bounds__(256) void cvt_resw_kernel(
    const float* __restrict__ res_w) {
    int idx = (blockIdx.x * 256 + threadIdx.x) * 4;
    float4 v = *(const float4*)(res_w + idx);
    __half2* dst = (__half2*)(d_rwh + idx);
    dst[0] = __floats2half2_rn(v.x, v.y);
    dst[1] = __floats2half2_rn(v.z, v.w);
}

// ---------------------------------------------------------------------------
// Kernel 1b: G2h[h][o*25+w][v*16+c] = sum_k wg*BnA, fp16 (k' = v-major).
// ---------------------------------------------------------------------------
__global__ __launch_bounds__(256) void gbuild_kernel(
    const float* __restrict__ w_block) {
    int o = blockIdx.x;   // 0..32 (32 = row-pad block)
    int h = blockIdx.y;
    int tid = threadIdx.x;
    if (o == 32) {
        __half* dst = d_G2h + (h * 896 + 800) * 400;
        for (int idx = tid; idx < 96 * 400; idx += 256) dst[idx] = __half(0.f);
        return;
    }
    __shared__ float bna[3 * 625];
    __shared__ float wg3[48];
    for (int idx = tid; idx < 1875; idx += 256) {
        int k = idx / 625;
        bna[idx] = d_BnA[(k * 8 + h) * 625 + (idx - k * 625)];
    }
    if (tid < 48) {
        int k = tid / 16, c = tid & 15;
        wg3[tid] = w_block[(k * 8 + h) * 512 + o * 16 + c];
    }
    __syncthreads();
    __half* dst = d_G2h + (h * 896 + o * 25) * 400;
    for (int idx = tid; idx < 10000; idx += 256) {   // 25 w x 400 k'
        int w = idx / 400, r = idx - w * 400;
        int v = r >> 4, c = r & 15;
        int vw = v * 25 + w;
        float val = wg3[c] * bna[vw] + wg3[16 + c] * bna[625 + vw] +
                    wg3[32 + c] * bna[1250 + vw];
        dst[w * 400 + r] = __float2half_rn(val);
    }
}

// ---------------------------------------------------------------------------
// Kernel 1c: x prep (xth only). Grid (16 n, 8 h, 8 tc).
// d_xth[n][tv][h*16+c], 16c x 400tv slab per CTA via smem transpose.
// ---------------------------------------------------------------------------
__global__ __launch_bounds__(256) void xprep_kernel(const float* __restrict__ x) {
    __shared__ __align__(16) float xs[16 * 404];
    int n = blockIdx.x, h = blockIdx.y, tc = blockIdx.z;
    int tid = threadIdx.x;
    const float* xb = x + n * CTV + h * 16 * TV + tc * 400;

    // Load slab: 16 rows x 400 floats = 1600 float4
#pragma unroll
    for (int it = 0; it < 7; ++it) {
        int idx = tid + it * 256;
        if (idx < 1600) {
            int c = idx / 100, f = idx - c * 100;
            *(float4*)(xs + c * 404 + f * 4) = *(const float4*)(xb + c * TV + f * 4);
        }
    }
    __syncthreads();

    // d_xth: 400 items = (200 tv-pairs) x (2 q-halves)
#pragma unroll
    for (int it = 0; it < 2; ++it) {
        int id = tid + it * 256;
        if (id < 400) {
            int tvp = id >> 1, q = id & 1;
            __half hA[8], hB[8];
#pragma unroll
            for (int cc = 0; cc < 8; ++cc) {
                float2 v = *(const float2*)&xs[(q * 8 + cc) * 404 + tvp * 2];
                hA[cc] = __float2half_rn(v.x);
                hB[cc] = __float2half_rn(v.y);
            }
            __half* base = d_xth + (n * 3200 + tc * 400 + tvp * 2) * 128 + h * 16 + q * 8;
            *(uint4*)base = *(uint4*)hA;
            *(uint4*)(base + 128) = *(uint4*)hB;
        }
    }
}

// ---------------------------------------------------------------------------
// Kernel 2: res GEMM fp16 m16n8k16, ldmatrix + cp.async staging. (validated)
// ---------------------------------------------------------------------------
#define RES_SMEM_BYTES (34816 * 2 + 2048)

__global__ __launch_bounds__(256, 2) void res_gemm_tc(
    const float* __restrict__ res_b) {
    extern __shared__ __align__(16) char smem[];
    __half* As = (__half*)smem;                 // [o 128][136]
    __half* Bs = (__half*)(smem + 34816);       // [tv 128][136]
    float* part = (float*)(smem + 69632);

    const int tid = threadIdx.x;
    const int wid = tid >> 5, lane = tid & 31;
    const int gid = lane >> 2, tg = lane & 3;
    const int warp_m = wid >> 1;
    const int warp_n = wid & 1;
    const int tv0 = blockIdx.x * 128;
    const int o0 = blockIdx.y * 128;
    const int n = blockIdx.z;

    {
        uint32_t As_u = s2u(As), Bs_u = s2u(Bs);
        const uint4* srcA = (const uint4*)(d_rwh + o0 * 128);
        const uint4* srcB = (const uint4*)(d_xth + (n * 3200 + tv0) * 128);
#pragma unroll
        for (int it = 0; it < 8; ++it) {
            int idx = tid + it * 256;            // 0..2047
            int row = idx >> 4, f = idx & 15;
            cp16(As_u + row * 272 + f * 16, srcA + row * 16 + f);
            cp16(Bs_u + row * 272 + f * 16, srcB + row * 16 + f);
        }
        CP_COMMIT();
        CP_WAIT(0);
    }
    __syncthreads();

    float c[2][8][4];
#pragma unroll
    for (int mt = 0; mt < 2; ++mt)
#pragma unroll
        for (int nt = 0; nt < 8; ++nt)
#pragma unroll
            for (int q = 0; q < 4; ++q) c[mt][nt][q] = 0.f;

    uint32_t aAddr[2], bAddr[4];
    {
        uint32_t As_u = s2u(As), Bs_u = s2u(Bs);
        int r8 = (lane & 7);
#pragma unroll
        for (int mt = 0; mt < 2; ++mt) {
            int row = warp_m * 32 + mt * 16 + r8 + ((lane & 8) ? 8 : 0);
            aAddr[mt] = As_u + row * 272 + ((lane & 16) ? 16 : 0);
        }
#pragma unroll
        for (int p = 0; p < 4; ++p) {
            int row = warp_n * 64 + p * 16 + r8 + ((lane & 16) ? 8 : 0);
            bAddr[p] = Bs_u + row * 272 + ((lane & 8) ? 16 : 0);
        }
    }

#pragma unroll
    for (int step = 0; step < 8; ++step) {
        uint32_t a[2][4], b[8][2];
#pragma unroll
        for (int mt = 0; mt < 2; ++mt)
            LDSM4(a[mt][0], a[mt][1], a[mt][2], a[mt][3], aAddr[mt] + step * 32);
#pragma unroll
        for (int p = 0; p < 4; ++p) {
            uint32_t r0, r1, r2, r3;
            LDSM4(r0, r1, r2, r3, bAddr[p] + step * 32);
            b[2 * p][0] = r0;  b[2 * p][1] = r1;
            b[2 * p + 1][0] = r2;  b[2 * p + 1][1] = r3;
        }
#pragma unroll
        for (int mt = 0; mt < 2; ++mt)
#pragma unroll
            for (int nt = 0; nt < 8; ++nt)
                mma_f16(c[mt][nt], a[mt], b[nt]);
    }

    const int colbase = tv0 + warp_n * 64 + 2 * tg;
#pragma unroll
    for (int mt = 0; mt < 2; ++mt) {
        int row0 = o0 + warp_m * 32 + mt * 16 + gid;
        float bias0 = res_b[row0];
        float bias1 = res_b[row0 + 8];
        float s0 = 0.f, q0 = 0.f, s1 = 0.f, q1 = 0.f;
        __half* dst0 = d_res_preh + (n * 256 + row0) * TV;
        __half* dst1 = dst0 + 8 * TV;
#pragma unroll
        for (int nt = 0; nt < 8; ++nt) {
            float v0 = c[mt][nt][0] + bias0;
            float v1 = c[mt][nt][1] + bias0;
            float v2 = c[mt][nt][2] + bias1;
            float v3 = c[mt][nt][3] + bias1;
            s0 += v0 + v1;  q0 += v0 * v0 + v1 * v1;
            s1 += v2 + v3;  q1 += v2 * v2 + v3 * v3;
            int col = colbase + nt * 8;
            *(__half2*)(dst0 + col) = __floats2half2_rn(v0, v1);
            *(__half2*)(dst1 + col) = __floats2half2_rn(v2, v3);
        }
#pragma unroll
        for (int off = 1; off <= 2; off <<= 1) {
            s0 += __shfl_xor_sync(0xFFFFFFFFu, s0, off);
            q0 += __shfl_xor_sync(0xFFFFFFFFu, q0, off);
            s1 += __shfl_xor_sync(0xFFFFFFFFu, s1, off);
            q1 += __shfl_xor_sync(0xFFFFFFFFu, q1, off);
        }
        if (tg == 0) {
            int r = warp_m * 32 + mt * 16 + gid;
            part[(warp_n * 128 + r) * 2] = s0;
            part[(warp_n * 128 + r) * 2 + 1] = q0;
            part[(warp_n * 128 + r + 8) * 2] = s1;
            part[(warp_n * 128 + r + 8) * 2 + 1] = q1;
        }
    }
    __syncthreads();
    if (tid < 128) {
        float s = part[tid * 2] + part[(128 + tid) * 2];
        float q = part[tid * 2 + 1] + part[(128 + tid) * 2 + 1];
        int blk = (n * 2 + blockIdx.y) * 25 + blockIdx.x;
        d_rpart[blk * 256 + tid * 2] = s;
        d_rpart[blk * 256 + tid * 2 + 1] = q;
    }
}

// ---------------------------------------------------------------------------
// Kernel 3: main fused GEMM fp16, k' = v*16+c; B staged straight from d_xth.
// Double-buffered cp.async. Buffers: A0@0, B0@22528, A1@45056, B1@67584.
// ---------------------------------------------------------------------------
#define MAIN_SMEM_BYTES (90112 + 2048)
#define BUFSZ 45056

__global__ __launch_bounds__(256, 2) void main_gemm_tc() {
    extern __shared__ __align__(16) char smem[];
    float* part = (float*)(smem + 90112);

    const int tid = threadIdx.x;
    const int wid = tid >> 5, lane = tid & 31;
    const int gid = lane >> 2, tg = lane & 3;
    const int warp_m = wid >> 1;
    const int warp_n = wid & 1;
    const int n = blockIdx.x;
    const int mb = blockIdx.y;
    const int m0 = mb * 128;
    const int h = blockIdx.z;

    float c[2][8][4];
#pragma unroll
    for (int mt = 0; mt < 2; ++mt)
#pragma unroll
        for (int nt = 0; nt < 8; ++nt)
#pragma unroll
            for (int q = 0; q < 4; ++q) c[mt][nt][q] = 0.f;

    const uint32_t smem_u = s2u(smem);
    const __half* gbase = d_G2h + (h * 896 + m0) * 400;
    const __half* xthn = d_xth + n * 3200 * 128 + h * 16;   // + (t*25+v)*128

    uint32_t aAddr[2], bAddr[4];
    {
        int r8 = (lane & 7);
#pragma unroll
        for (int mt = 0; mt < 2; ++mt) {
            int row = warp_m * 32 + mt * 16 + r8 + ((lane & 8) ? 8 : 0);
            aAddr[mt] = smem_u + row * 176 + ((lane & 16) ? 16 : 0);
        }
#pragma unroll
        for (int p = 0; p < 4; ++p) {
            int row = warp_n * 64 + p * 16 + r8 + ((lane & 16) ? 8 : 0);
            bAddr[p] = smem_u + 22528 + row * 176 + ((lane & 8) ? 16 : 0);
        }
    }

    // per-thread staging indices: idx = tid + it*256, row = idx/10, r = idx%10
    // A: f = r (0..9): 16B at gbase + row*400 + kc + r*8 (halves)
    // B: v = r>>1, q16 = r&1: 16B at xthn + (row*25 + 5q + v)*128 + q16*8

    // issue chunk 0 into buffer 0
    {
#pragma unroll
        for (int it = 0; it < 5; ++it) {
            int idx = tid + it * 256;
            int row = idx / 10, r = idx - row * 10;
            cp16(smem_u + row * 176 + r * 16, gbase + row * 400 + r * 8);
            int v = r >> 1, q16 = r & 1;
            cp16(smem_u + 22528 + row * 176 + v * 32 + q16 * 16,
                 xthn + (row * 25 + v) * 128 + q16 * 8);
        }
        CP_COMMIT();
    }

    for (int q = 0; q < 5; ++q) {
        const int buf = q & 1;
        if (q + 1 < 5) {
            const int nb = (q + 1) & 1;
            const int kc = (q + 1) * 80;
            const int vb = (q + 1) * 5;
#pragma unroll
            for (int it = 0; it < 5; ++it) {
                int idx = tid + it * 256;
                int row = idx / 10, r = idx - row * 10;
                cp16(smem_u + nb * BUFSZ + row * 176 + r * 16,
                     gbase + row * 400 + kc + r * 8);
                int v = r >> 1, q16 = r & 1;
                cp16(smem_u + nb * BUFSZ + 22528 + row * 176 + v * 32 + q16 * 16,
                     xthn + (row * 25 + vb + v) * 128 + q16 * 8);
            }
            CP_COMMIT();
            CP_WAIT(1);
        } else {
            CP_WAIT(0);
        }
        __syncthreads();

        const uint32_t boff = buf * BUFSZ;
#pragma unroll
        for (int step = 0; step < 5; ++step) {
            uint32_t a[2][4], b[8][2];
#pragma unroll
            for (int mt = 0; mt < 2; ++mt)
                LDSM4(a[mt][0], a[mt][1], a[mt][2], a[mt][3],
                      aAddr[mt] + boff + step * 32);
#pragma unroll
            for (int p = 0; p < 4; ++p) {
                uint32_t r0, r1, r2, r3;
                LDSM4(r0, r1, r2, r3, bAddr[p] + boff + step * 32);
                b[2 * p][0] = r0;  b[2 * p][1] = r1;
                b[2 * p + 1][0] = r2;  b[2 * p + 1][1] = r3;
            }
#pragma unroll
            for (int mt = 0; mt < 2; ++mt)
#pragma unroll
                for (int nt = 0; nt < 8; ++nt)
                    mma_f16(c[mt][nt], a[mt], b[nt]);
        }
        __syncthreads();
    }

    // Epilogue: bias, canonical-layout fp16 stores, BN partials.
    __half* obase = d_out_preh + (n * 256 + h * 32) * TV;
#pragma unroll
    for (int mt = 0; mt < 2; ++mt) {
        int r0 = m0 + warp_m * 32 + mt * 16 + gid;
        int r1 = r0 + 8;
        int o0 = r0 / 25, o1 = r1 / 25;
        int w0 = r0 - o0 * 25, w1 = r1 - o1 * 25;
        float bias0 = (r0 < 800) ? d_bsum[h * 32 + o0] : 0.f;
        float bias1 = (r1 < 800) ? d_bsum[h * 32 + o1] : 0.f;
        float s0 = 0.f, q0 = 0.f, s1 = 0.f, q1 = 0.f;
        int colbase = warp_n * 64 + 2 * tg;
#pragma unroll
        for (int nt = 0; nt < 8; ++nt) {
            float v0 = c[mt][nt][0] + bias0;
            float v1 = c[mt][nt][1] + bias0;
            float v2 = c[mt][nt][2] + bias1;
            float v3 = c[mt][nt][3] + bias1;
            s0 += v0 + v1;  q0 += v0 * v0 + v1 * v1;
            s1 += v2 + v3;  q1 += v2 * v2 + v3 * v3;
            int col = colbase + nt * 8;         // t index
            if (r0 < 800) {
                __half* d0 = obase + o0 * TV + col * 25 + w0;
                d0[0] = __float2half_rn(v0);
                d0[25] = __float2half_rn(v1);
            }
            if (r1 < 800) {
                __half* d1 = obase + o1 * TV + col * 25 + w1;
                d1[0] = __float2half_rn(v2);
                d1[25] = __float2half_rn(v3);
            }
        }
#pragma unroll
        for (int off = 1; off <= 2; off <<= 1) {
            s0 += __shfl_xor_sync(0xFFFFFFFFu, s0, off);
            q0 += __shfl_xor_sync(0xFFFFFFFFu, q0, off);
            s1 += __shfl_xor_sync(0xFFFFFFFFu, s1, off);
            q1 += __shfl_xor_sync(0xFFFFFFFFu, q1, off);
        }
        if (tg == 0) {
            int r = warp_m * 32 + mt * 16 + gid;
            part[(warp_n * 128 + r) * 2] = s0;
            part[(warp_n * 128 + r) * 2 + 1] = q0;
            part[(warp_n * 128 + r + 8) * 2] = s1;
            part[(warp_n * 128 + r + 8) * 2 + 1] = q1;
        }
    }
    __syncthreads();
    if (tid < 128) {
        float s = part[tid * 2] + part[(128 + tid) * 2];
        float q = part[tid * 2 + 1] + part[(128 + tid) * 2 + 1];
        int blk = (h * 7 + mb) * 16 + n;
        d_mpart[(blk * 128 + tid) * 2] = s;
        d_mpart[(blk * 128 + tid) * 2 + 1] = q;
    }
}

// ---------------------------------------------------------------------------
// Kernel 4: merged BN stats (both paths). Grid 512: which = blk>>8.
// ---------------------------------------------------------------------------
__global__ __launch_bounds__(128) void stats_kernel(
    const float* __restrict__ bn_gamma, const float* __restrict__ bn_beta,
    const float* __restrict__ res_bn_gamma, const float* __restrict__ res_bn_beta) {
    __shared__ float ssum[128];
    __shared__ float ssq[128];
    int which = blockIdx.x >> 8;
    int ch = blockIdx.x & 255;
    int tid = threadIdx.x;

    float s = 0.f, q = 0.f;
    if (which == 0) {
        int h = ch >> 5, o = ch & 31;
        for (int e = tid; e < 400; e += 128) {
            int w = e >> 4, nn = e & 15;
            int grow = o * 25 + w;
            int mb = grow >> 7, lr = grow & 127;
            int blk = (h * 7 + mb) * 16 + nn;
            s += d_mpart[(blk * 128 + lr) * 2];
            q += d_mpart[(blk * 128 + lr) * 2 + 1];
        }
    } else {
        int ob = ch >> 7, row = ch & 127;
        for (int e = tid; e < 400; e += 128) {
            int nn = e / 25, tvb = e - nn * 25;
            int blk = (nn * 2 + ob) * 25 + tvb;
            s += d_rpart[blk * 256 + row * 2];
            q += d_rpart[blk * 256 + row * 2 + 1];
        }
    }
    ssum[tid] = s;
    ssq[tid] = q;
    __syncthreads();
    for (int st = 64; st > 0; st >>= 1) {
        if (tid < st) {
            ssum[tid] += ssum[tid + st];
            ssq[tid] += ssq[tid + st];
        }
        __syncthreads();
    }
    if (tid == 0) {
        const float inv = 1.f / 51200.f;
        float mean = ssum[0] * inv;
        float var = ssq[0] * inv - mean * mean;
        float g = which ? res_bn_gamma[ch] : bn_gamma[ch];
        float b = which ? res_bn_beta[ch] : bn_beta[ch];
        float sc = g * rsqrtf(var + 1e-5f);
        d_ss[which * 512 + ch] = sc;
        d_ss[which * 512 + 256 + ch] = b - mean * sc;
    }
}

// ---------------------------------------------------------------------------
// Kernel 5: out = relu(BN(out_preh) + BN(res_preh)). Block per (n,ch).
// ---------------------------------------------------------------------------
__global__ __launch_bounds__(256) void final_kernel(float* __restrict__ out) {
    int b = blockIdx.x;                 // n*256 + ch
    int ch = b & 255;
    int tid = threadIdx.x;
    const uint2* po = (const uint2*)(d_out_preh + b * TV);
    const uint2* pr = (const uint2*)(d_res_preh + b * TV);
    float4* dst = (float4*)(out + b * TV);
    float so = d_ss[ch], ho = d_ss[256 + ch];
    float sr = d_ss[512 + ch], hr = d_ss[768 + ch];
#pragma unroll
    for (int it = 0; it < 4; ++it) {
        int idx = tid + it * 256;       // < 800 uint2 (4 halves each)
        if (idx < 800) {
            uint2 ov = po[idx];
            uint2 rv = pr[idx];
            float2 o0 = __half22float2(*(__half2*)&ov.x);
            float2 o1 = __half22float2(*(__half2*)&ov.y);
            float2 r0 = __half22float2(*(__half2*)&rv.x);
            float2 r1 = __half22float2(*(__half2*)&rv.y);
            float4 r;
            r.x = fmaxf(fmaf(o0.x, so, ho) + fmaf(r0.x, sr, hr), 0.f);
            r.y = fmaxf(fmaf(o0.y, so, ho) + fmaf(r0.y, sr, hr), 0.f);
            r.z = fmaxf(fmaf(o1.x, so, ho) + fmaf(r1.x, sr, hr), 0.f);
            r.w = fmaxf(fmaf(o1.y, so, ho) + fmaf(r1.y, sr, hr), 0.f);
            dst[idx] = r;
        }
    }
}

// ---------------------------------------------------------------------------
extern "C" void kernel_launch(void* const* d_in, const int* in_sizes, int n_in,
                              void* d_out, int out_size) {
    const float* x            = (const float*)d_in[0];
    const int*   hop          = (const int*)d_in[1];
    const float* emb          = (const float*)d_in[2];
    const float* A            = (const float*)d_in[3];
    const float* w_block      = (const float*)d_in[4];
    const float* b_block      = (const float*)d_in[5];
    const float* bn_gamma     = (const float*)d_in[6];
    const float* bn_beta      = (const float*)d_in[7];
    const float* res_w        = (const float*)d_in[8];
    const float* res_b        = (const float*)d_in[9];
    const float* res_bn_gamma = (const float*)d_in[10];
    const float* res_bn_beta  = (const float*)d_in[11];
    float* out = (float*)d_out;

    cudaFuncSetAttribute(res_gemm_tc, cudaFuncAttributeMaxDynamicSharedMemorySize,
                         RES_SMEM_BYTES);
    cudaFuncSetAttribute(main_gemm_tc, cudaFuncAttributeMaxDynamicSharedMemorySize,
                         MAIN_SMEM_BYTES);

    prep_kernel<<<25, 32>>>(hop, emb, A, b_block);
    cvt_resw_kernel<<<32, 256>>>(res_w);
    gbuild_kernel<<<dim3(33, 8), 256>>>(w_block);
    xprep_kernel<<<dim3(16, 8, 8), 256>>>(x);
    res_gemm_tc<<<dim3(25, 2, 16), 256, RES_SMEM_BYTES>>>(res_b);
    main_gemm_tc<<<dim3(16, 7, 8), 256, MAIN_SMEM_BYTES>>>();
    stats_kernel<<<512, 128>>>(bn_gamma, bn_beta, res_bn_gamma, res_bn_beta);
    final_kernel<<<4096, 256>>>(out);
}

// round 14
// speedup vs baseline: 1.0686x; 1.0686x over previous
#include <cuda_runtime.h>
#include <cuda_fp16.h>
#include <math.h>
#include <stdint.h>

// Problem constants
// N=16, C=128, T=128, V=25, K=3, H=8, OC=256, C/H=16, OC/H=32
// x: (16,128,128,25)  out: (16,256,128,25)

#define TV 3200          // T*V
#define CTV 409600       // C*T*V

// ---- scratch (device globals; allocation-free) ----
__device__ float d_BnA[24 * 625];
__device__ float d_bsum[256];
__device__ __align__(16) __half d_res_preh[16 * 256 * 3200];   // [n][ch][t][w]
__device__ __align__(16) __half d_out_preh[16 * 256 * 3200];   // [n][ch][t][w]
__device__ __align__(16) __half d_G2h[8 * 896 * 400];   // fused weights, k=c*25+v
__device__ __align__(16) __half d_xrh[16 * 8 * 128 * 400]; // x for main GEMM
__device__ __align__(16) __half d_xth[16 * 3200 * 128];    // x for res GEMM
__device__ __align__(16) __half d_rwh[256 * 128];          // res_w fp16
__device__ float d_ss[1024];
__device__ float d_rpart[800 * 256];             // res-path BN partials
__device__ float d_mpart[8 * 7 * 16 * 128 * 2];  // main-path BN partials

__device__ __forceinline__ void mma_f16(float c[4], const uint32_t a[4],
                                        const uint32_t b[2]) {
    asm volatile(
        "mma.sync.aligned.m16n8k16.row.col.f32.f16.f16.f32 "
        "{%0,%1,%2,%3},{%4,%5,%6,%7},{%8,%9},{%0,%1,%2,%3};"
        : "+f"(c[0]), "+f"(c[1]), "+f"(c[2]), "+f"(c[3])
        : "r"(a[0]), "r"(a[1]), "r"(a[2]), "r"(a[3]), "r"(b[0]), "r"(b[1]));
}
__device__ __forceinline__ uint32_t s2u(const void* p) {
    return (uint32_t)__cvta_generic_to_shared(p);
}
#define LDSM4(r0, r1, r2, r3, addr)                                        \
    asm volatile("ldmatrix.sync.aligned.m8n8.x4.shared.b16 {%0,%1,%2,%3},[%4];" \
                 : "=r"(r0), "=r"(r1), "=r"(r2), "=r"(r3) : "r"(addr))
__device__ __forceinline__ void cp16(uint32_t dst, const void* src) {
    asm volatile("cp.async.cg.shared.global [%0], [%1], 16;"
                 :: "r"(dst), "l"(src));
}
#define CP_COMMIT() asm volatile("cp.async.commit_group;" ::: "memory")
#define CP_WAIT(n)  asm volatile("cp.async.wait_group %0;" :: "n"(n) : "memory")

// ---------------------------------------------------------------------------
// Kernel 1: build BnA and summed bias.
// ---------------------------------------------------------------------------
__global__ void prep_kernel(const int* __restrict__ hop,
                            const float* __restrict__ emb,
                            const float* __restrict__ A,
                            const float* __restrict__ b_block) {
    int g = blockIdx.x;
    int w = threadIdx.x;
    if (g < 24) {
        if (w < 25) {
            const float* eg = emb + g * 12;
            const float* Ag = A + g * 625;
            float sb = 0.f, sa = 0.f;
            for (int v = 0; v < 25; ++v) {
                float bv = eg[hop[v * 25 + w]];
                float av = Ag[v * 25 + w];
                sb += bv * bv;
                sa += av * av;
            }
            float rb = 1.f / (sqrtf(sb) + 1e-4f);
            float ra = 1.f / (sqrtf(sa) + 1e-4f);
            for (int v = 0; v < 25; ++v) {
                float bv = eg[hop[v * 25 + w]];
                float av = Ag[v * 25 + w];
                d_BnA[g * 625 + v * 25 + w] = bv * rb + av * ra;
            }
        }
    } else {
        for (int oc = w; oc < 256; oc += 32)
            d_bsum[oc] = b_block[oc] + b_block[256 + oc] + b_block[512 + oc];
    }
}

// ---------------------------------------------------------------------------
// Kernel 1a: convert res_w -> fp16.
// ---------------------------------------------------------------------------
__global__ __launch_bounds__(256) void cvt_resw_kernel(
    const float* __restrict__ res_w) {
    int idx = (blockIdx.x * 256 + threadIdx.x) * 4;
    float4 v = *(const float4*)(res_w + idx);
    __half2* dst = (__half2*)(d_rwh + idx);
    dst[0] = __floats2half2_rn(v.x, v.y);
    dst[1] = __floats2half2_rn(v.z, v.w);
}

// ---------------------------------------------------------------------------
// Kernel 1b: G2h[h][o*25+w][c*25+v] = sum_k wg*BnA, fp16 (k = c-major, r12).
// ---------------------------------------------------------------------------
__global__ __launch_bounds__(256) void gbuild_kernel(
    const float* __restrict__ w_block) {
    int o = blockIdx.x;   // 0..32 (32 = row-pad block)
    int h = blockIdx.y;
    int tid = threadIdx.x;
    if (o == 32) {
        __half* dst = d_G2h + (h * 896 + 800) * 400;
        for (int idx = tid; idx < 96 * 400; idx += 256) dst[idx] = __half(0.f);
        return;
    }
    __shared__ float bna[3 * 625];
    __shared__ float wg3[48];
    for (int idx = tid; idx < 1875; idx += 256) {
        int k = idx / 625;
        bna[idx] = d_BnA[(k * 8 + h) * 625 + (idx - k * 625)];
    }
    if (tid < 48) {
        int k = tid / 16, c = tid & 15;
        wg3[tid] = w_block[(k * 8 + h) * 512 + o * 16 + c];
    }
    __syncthreads();
    __half* dst = d_G2h + (h * 896 + o * 25) * 400;
    for (int idx = tid; idx < 10000; idx += 256) {   // 25 w x 400 cv
        int w = idx / 400, cv = idx - w * 400;
        int c = cv / 25, v = cv - c * 25;
        int vw = v * 25 + w;
        float val = wg3[c] * bna[vw] + wg3[16 + c] * bna[625 + vw] +
                    wg3[32 + c] * bna[1250 + vw];
        dst[w * 400 + cv] = __float2half_rn(val);
    }
}

// ---------------------------------------------------------------------------
// Kernel 1c: unified x prep (r12). Grid (16 n, 8 h, 8 tc).
// ---------------------------------------------------------------------------
__global__ __launch_bounds__(256) void xprep_kernel(const float* __restrict__ x) {
    __shared__ __align__(16) float xs[16 * 404];
    int n = blockIdx.x, h = blockIdx.y, tc = blockIdx.z;
    int tid = threadIdx.x;
    const float* xb = x + n * CTV + h * 16 * TV + tc * 400;

#pragma unroll
    for (int it = 0; it < 7; ++it) {
        int idx = tid + it * 256;
        if (idx < 1600) {
            int c = idx / 100, f = idx - c * 100;
            *(float4*)(xs + c * 404 + f * 4) = *(const float4*)(xb + c * TV + f * 4);
        }
    }
    __syncthreads();

    // d_xth[n][tv][h*16+c]
#pragma unroll
    for (int it = 0; it < 2; ++it) {
        int id = tid + it * 256;
        if (id < 400) {
            int tvp = id >> 1, q = id & 1;
            __half hA[8], hB[8];
#pragma unroll
            for (int cc = 0; cc < 8; ++cc) {
                float2 v = *(const float2*)&xs[(q * 8 + cc) * 404 + tvp * 2];
                hA[cc] = __float2half_rn(v.x);
                hB[cc] = __float2half_rn(v.y);
            }
            __half* base = d_xth + (n * 3200 + tc * 400 + tvp * 2) * 128 + h * 16 + q * 8;
            *(uint4*)base = *(uint4*)hA;
            *(uint4*)(base + 128) = *(uint4*)hB;
        }
    }
    // d_xrh[n][h][t][c*25+v]: thread owns one half2 column, marches t.
    if (tid < 200) {
        int k0 = tid * 2;
        int c0 = k0 / 25, v0 = k0 - c0 * 25;
        int c1 = (v0 == 24) ? c0 + 1 : c0;
        int v1 = (v0 == 24) ? 0 : v0 + 1;
        const float* p0 = &xs[c0 * 404 + v0];
        const float* p1 = &xs[c1 * 404 + v1];
        __half2* dstr = (__half2*)(d_xrh + ((n * 8 + h) * 128 + tc * 16) * 400);
#pragma unroll
        for (int t = 0; t < 16; ++t)
            dstr[t * 200 + tid] = __floats2half2_rn(p0[t * 25], p1[t * 25]);
    }
}

// ---------------------------------------------------------------------------
// Kernel 2+3 FUSED: one launch, 1696 CTAs. bid < 896 -> main GEMM (r12 body,
// double-buffered cp.async); bid >= 896 -> res GEMM (r12 body). Main first so
// its tail overlaps res CTAs. smem = union (main's 92 KB layout).
// ---------------------------------------------------------------------------
#define FUSED_SMEM_BYTES (90112 + 2048)
#define BUFSZ 45056

__global__ __launch_bounds__(256, 2) void gemm_fused(
    const float* __restrict__ res_b) {
    extern __shared__ __align__(16) char smem[];
    float* part = (float*)(smem + 90112);

    const int tid = threadIdx.x;
    const int wid = tid >> 5, lane = tid & 31;
    const int gid = lane >> 2, tg = lane & 3;
    const int warp_m = wid >> 1;
    const int warp_n = wid & 1;
    const uint32_t smem_u = s2u(smem);
    const int r8 = (lane & 7);

    float c[2][8][4];
#pragma unroll
    for (int mt = 0; mt < 2; ++mt)
#pragma unroll
        for (int nt = 0; nt < 8; ++nt)
#pragma unroll
            for (int q = 0; q < 4; ++q) c[mt][nt][q] = 0.f;

    if (blockIdx.x < 896) {
        // ================= MAIN GEMM =================
        const int mid = blockIdx.x;
        const int n = mid & 15;
        const int mb = (mid >> 4) % 7;
        const int m0 = mb * 128;
        const int h = mid / 112;

        const __half* gbase = d_G2h + (h * 896 + m0) * 400;
        const __half* xbase = d_xrh + (n * 8 + h) * 128 * 400;

        uint32_t aAddr[2], bAddr[4];
#pragma unroll
        for (int mt = 0; mt < 2; ++mt) {
            int row = warp_m * 32 + mt * 16 + r8 + ((lane & 8) ? 8 : 0);
            aAddr[mt] = smem_u + row * 176 + ((lane & 16) ? 16 : 0);
        }
#pragma unroll
        for (int p = 0; p < 4; ++p) {
            int row = warp_n * 64 + p * 16 + r8 + ((lane & 16) ? 8 : 0);
            bAddr[p] = smem_u + 22528 + row * 176 + ((lane & 8) ? 16 : 0);
        }

        // issue chunk 0 into buffer 0
#pragma unroll
        for (int it = 0; it < 5; ++it) {
            int idx = tid + it * 256;
            int row = idx / 10, f = idx - row * 10;
            cp16(smem_u + row * 176 + f * 16, gbase + row * 400 + f * 8);
            cp16(smem_u + 22528 + row * 176 + f * 16, xbase + row * 400 + f * 8);
        }
        CP_COMMIT();

        for (int q = 0; q < 5; ++q) {
            const int buf = q & 1;
            if (q + 1 < 5) {
                const int nb = (q + 1) & 1;
                const int kc = (q + 1) * 80;
#pragma unroll
                for (int it = 0; it < 5; ++it) {
                    int idx = tid + it * 256;
                    int row = idx / 10, f = idx - row * 10;
                    cp16(smem_u + nb * BUFSZ + row * 176 + f * 16,
                         gbase + row * 400 + kc + f * 8);
                    cp16(smem_u + nb * BUFSZ + 22528 + row * 176 + f * 16,
                         xbase + row * 400 + kc + f * 8);
                }
                CP_COMMIT();
                CP_WAIT(1);
            } else {
                CP_WAIT(0);
            }
            __syncthreads();

            const uint32_t boff = buf * BUFSZ;
#pragma unroll
            for (int step = 0; step < 5; ++step) {
                uint32_t a[2][4], b[8][2];
#pragma unroll
                for (int mt = 0; mt < 2; ++mt)
                    LDSM4(a[mt][0], a[mt][1], a[mt][2], a[mt][3],
                          aAddr[mt] + boff + step * 32);
#pragma unroll
                for (int p = 0; p < 4; ++p) {
                    uint32_t r0, r1, r2, r3;
                    LDSM4(r0, r1, r2, r3, bAddr[p] + boff + step * 32);
                    b[2 * p][0] = r0;  b[2 * p][1] = r1;
                    b[2 * p + 1][0] = r2;  b[2 * p + 1][1] = r3;
                }
#pragma unroll
                for (int mt = 0; mt < 2; ++mt)
#pragma unroll
                    for (int nt = 0; nt < 8; ++nt)
                        mma_f16(c[mt][nt], a[mt], b[nt]);
            }
            __syncthreads();
        }

        // Epilogue
        __half* obase = d_out_preh + (n * 256 + h * 32) * TV;
#pragma unroll
        for (int mt = 0; mt < 2; ++mt) {
            int r0 = m0 + warp_m * 32 + mt * 16 + gid;
            int r1 = r0 + 8;
            int o0 = r0 / 25, o1 = r1 / 25;
            int w0 = r0 - o0 * 25, w1 = r1 - o1 * 25;
            float bias0 = (r0 < 800) ? d_bsum[h * 32 + o0] : 0.f;
            float bias1 = (r1 < 800) ? d_bsum[h * 32 + o1] : 0.f;
            float s0 = 0.f, q0 = 0.f, s1 = 0.f, q1 = 0.f;
            int colbase = warp_n * 64 + 2 * tg;
#pragma unroll
            for (int nt = 0; nt < 8; ++nt) {
                float v0 = c[mt][nt][0] + bias0;
                float v1 = c[mt][nt][1] + bias0;
                float v2 = c[mt][nt][2] + bias1;
                float v3 = c[mt][nt][3] + bias1;
                s0 += v0 + v1;  q0 += v0 * v0 + v1 * v1;
                s1 += v2 + v3;  q1 += v2 * v2 + v3 * v3;
                int col = colbase + nt * 8;
                if (r0 < 800) {
                    __half* d0 = obase + o0 * TV + col * 25 + w0;
                    d0[0] = __float2half_rn(v0);
                    d0[25] = __float2half_rn(v1);
                }
                if (r1 < 800) {
                    __half* d1 = obase + o1 * TV + col * 25 + w1;
                    d1[0] = __float2half_rn(v2);
                    d1[25] = __float2half_rn(v3);
                }
            }
#pragma unroll
            for (int off = 1; off <= 2; off <<= 1) {
                s0 += __shfl_xor_sync(0xFFFFFFFFu, s0, off);
                q0 += __shfl_xor_sync(0xFFFFFFFFu, q0, off);
                s1 += __shfl_xor_sync(0xFFFFFFFFu, s1, off);
                q1 += __shfl_xor_sync(0xFFFFFFFFu, q1, off);
            }
            if (tg == 0) {
                int r = warp_m * 32 + mt * 16 + gid;
                part[(warp_n * 128 + r) * 2] = s0;
                part[(warp_n * 128 + r) * 2 + 1] = q0;
                part[(warp_n * 128 + r + 8) * 2] = s1;
                part[(warp_n * 128 + r + 8) * 2 + 1] = q1;
            }
        }
        __syncthreads();
        if (tid < 128) {
            float s = part[tid * 2] + part[(128 + tid) * 2];
            float q = part[tid * 2 + 1] + part[(128 + tid) * 2 + 1];
            int blk = (h * 7 + mb) * 16 + n;
            d_mpart[(blk * 128 + tid) * 2] = s;
            d_mpart[(blk * 128 + tid) * 2 + 1] = q;
        }
    } else {
        // ================= RES GEMM =================
        const int rid = blockIdx.x - 896;
        const int tvb = rid % 25;
        const int ob = (rid / 25) & 1;
        const int n = rid / 50;
        const int tv0 = tvb * 128;
        const int o0 = ob * 128;

        __half* As = (__half*)smem;                 // [o 128][136]
        __half* Bs = (__half*)(smem + 34816);       // [tv 128][136]

        {
            const uint4* srcA = (const uint4*)(d_rwh + o0 * 128);
            const uint4* srcB = (const uint4*)(d_xth + (n * 3200 + tv0) * 128);
#pragma unroll
            for (int it = 0; it < 8; ++it) {
                int idx = tid + it * 256;
                int row = idx >> 4, f = idx & 15;
                cp16(smem_u + row * 272 + f * 16, srcA + row * 16 + f);
                cp16(smem_u + 34816 + row * 272 + f * 16, srcB + row * 16 + f);
            }
            CP_COMMIT();
            CP_WAIT(0);
        }
        __syncthreads();

        uint32_t aAddr[2], bAddr[4];
#pragma unroll
        for (int mt = 0; mt < 2; ++mt) {
            int row = warp_m * 32 + mt * 16 + r8 + ((lane & 8) ? 8 : 0);
            aAddr[mt] = smem_u + row * 272 + ((lane & 16) ? 16 : 0);
        }
#pragma unroll
        for (int p = 0; p < 4; ++p) {
            int row = warp_n * 64 + p * 16 + r8 + ((lane & 16) ? 8 : 0);
            bAddr[p] = smem_u + 34816 + row * 272 + ((lane & 8) ? 16 : 0);
        }

#pragma unroll
        for (int step = 0; step < 8; ++step) {
            uint32_t a[2][4], b[8][2];
#pragma unroll
            for (int mt = 0; mt < 2; ++mt)
                LDSM4(a[mt][0], a[mt][1], a[mt][2], a[mt][3], aAddr[mt] + step * 32);
#pragma unroll
            for (int p = 0; p < 4; ++p) {
                uint32_t r0, r1, r2, r3;
                LDSM4(r0, r1, r2, r3, bAddr[p] + step * 32);
                b[2 * p][0] = r0;  b[2 * p][1] = r1;
                b[2 * p + 1][0] = r2;  b[2 * p + 1][1] = r3;
            }
#pragma unroll
            for (int mt = 0; mt < 2; ++mt)
#pragma unroll
                for (int nt = 0; nt < 8; ++nt)
                    mma_f16(c[mt][nt], a[mt], b[nt]);
        }

        const int colbase = tv0 + warp_n * 64 + 2 * tg;
#pragma unroll
        for (int mt = 0; mt < 2; ++mt) {
            int row0 = o0 + warp_m * 32 + mt * 16 + gid;
            float bias0 = res_b[row0];
            float bias1 = res_b[row0 + 8];
            float s0 = 0.f, q0 = 0.f, s1 = 0.f, q1 = 0.f;
            __half* dst0 = d_res_preh + (n * 256 + row0) * TV;
            __half* dst1 = dst0 + 8 * TV;
#pragma unroll
            for (int nt = 0; nt < 8; ++nt) {
                float v0 = c[mt][nt][0] + bias0;
                float v1 = c[mt][nt][1] + bias0;
                float v2 = c[mt][nt][2] + bias1;
                float v3 = c[mt][nt][3] + bias1;
                s0 += v0 + v1;  q0 += v0 * v0 + v1 * v1;
                s1 += v2 + v3;  q1 += v2 * v2 + v3 * v3;
                int col = colbase + nt * 8;
                *(__half2*)(dst0 + col) = __floats2half2_rn(v0, v1);
                *(__half2*)(dst1 + col) = __floats2half2_rn(v2, v3);
            }
#pragma unroll
            for (int off = 1; off <= 2; off <<= 1) {
                s0 += __shfl_xor_sync(0xFFFFFFFFu, s0, off);
                q0 += __shfl_xor_sync(0xFFFFFFFFu, q0, off);
                s1 += __shfl_xor_sync(0xFFFFFFFFu, s1, off);
                q1 += __shfl_xor_sync(0xFFFFFFFFu, q1, off);
            }
            if (tg == 0) {
                int r = warp_m * 32 + mt * 16 + gid;
                part[(warp_n * 128 + r) * 2] = s0;
                part[(warp_n * 128 + r) * 2 + 1] = q0;
                part[(warp_n * 128 + r + 8) * 2] = s1;
                part[(warp_n * 128 + r + 8) * 2 + 1] = q1;
            }
        }
        __syncthreads();
        if (tid < 128) {
            float s = part[tid * 2] + part[(128 + tid) * 2];
            float q = part[tid * 2 + 1] + part[(128 + tid) * 2 + 1];
            int blk = (n * 2 + ob) * 25 + tvb;
            d_rpart[blk * 256 + tid * 2] = s;
            d_rpart[blk * 256 + tid * 2 + 1] = q;
        }
    }
}

// ---------------------------------------------------------------------------
// Kernel 4: merged BN stats (both paths). Grid 512: which = blk>>8.
// ---------------------------------------------------------------------------
__global__ __launch_bounds__(128) void stats_kernel(
    const float* __restrict__ bn_gamma, const float* __restrict__ bn_beta,
    const float* __restrict__ res_bn_gamma, const float* __restrict__ res_bn_beta) {
    __shared__ float ssum[128];
    __shared__ float ssq[128];
    int which = blockIdx.x >> 8;
    int ch = blockIdx.x & 255;
    int tid = threadIdx.x;

    float s = 0.f, q = 0.f;
    if (which == 0) {
        int h = ch >> 5, o = ch & 31;
        for (int e = tid; e < 400; e += 128) {
            int w = e >> 4, nn = e & 15;
            int grow = o * 25 + w;
            int mb = grow >> 7, lr = grow & 127;
            int blk = (h * 7 + mb) * 16 + nn;
            s += d_mpart[(blk * 128 + lr) * 2];
            q += d_mpart[(blk * 128 + lr) * 2 + 1];
        }
    } else {
        int ob = ch >> 7, row = ch & 127;
        for (int e = tid; e < 400; e += 128) {
            int nn = e / 25, tvb = e - nn * 25;
            int blk = (nn * 2 + ob) * 25 + tvb;
            s += d_rpart[blk * 256 + row * 2];
            q += d_rpart[blk * 256 + row * 2 + 1];
        }
    }
    ssum[tid] = s;
    ssq[tid] = q;
    __syncthreads();
    for (int st = 64; st > 0; st >>= 1) {
        if (tid < st) {
            ssum[tid] += ssum[tid + st];
            ssq[tid] += ssq[tid + st];
        }
        __syncthreads();
    }
    if (tid == 0) {
        const float inv = 1.f / 51200.f;
        float mean = ssum[0] * inv;
        float var = ssq[0] * inv - mean * mean;
        float g = which ? res_bn_gamma[ch] : bn_gamma[ch];
        float b = which ? res_bn_beta[ch] : bn_beta[ch];
        float sc = g * rsqrtf(var + 1e-5f);
        d_ss[which * 512 + ch] = sc;
        d_ss[which * 512 + 256 + ch] = b - mean * sc;
    }
}

// ---------------------------------------------------------------------------
// Kernel 5: out = relu(BN(out_preh) + BN(res_preh)). Block per (n,ch).
// ---------------------------------------------------------------------------
__global__ __launch_bounds__(256) void final_kernel(float* __restrict__ out) {
    int b = blockIdx.x;                 // n*256 + ch
    int ch = b & 255;
    int tid = threadIdx.x;
    const uint2* po = (const uint2*)(d_out_preh + b * TV);
    const uint2* pr = (const uint2*)(d_res_preh + b * TV);
    float4* dst = (float4*)(out + b * TV);
    float so = d_ss[ch], ho = d_ss[256 + ch];
    float sr = d_ss[512 + ch], hr = d_ss[768 + ch];
#pragma unroll
    for (int it = 0; it < 4; ++it) {
        int idx = tid + it * 256;       // < 800 uint2 (4 halves each)
        if (idx < 800) {
            uint2 ov = po[idx];
            uint2 rv = pr[idx];
            float2 o0 = __half22float2(*(__half2*)&ov.x);
            float2 o1 = __half22float2(*(__half2*)&ov.y);
            float2 r0 = __half22float2(*(__half2*)&rv.x);
            float2 r1 = __half22float2(*(__half2*)&rv.y);
            float4 r;
            r.x = fmaxf(fmaf(o0.x, so, ho) + fmaf(r0.x, sr, hr), 0.f);
            r.y = fmaxf(fmaf(o0.y, so, ho) + fmaf(r0.y, sr, hr), 0.f);
            r.z = fmaxf(fmaf(o1.x, so, ho) + fmaf(r1.x, sr, hr), 0.f);
            r.w = fmaxf(fmaf(o1.y, so, ho) + fmaf(r1.y, sr, hr), 0.f);
            dst[idx] = r;
        }
    }
}

// ---------------------------------------------------------------------------
extern "C" void kernel_launch(void* const* d_in, const int* in_sizes, int n_in,
                              void* d_out, int out_size) {
    const float* x            = (const float*)d_in[0];
    const int*   hop          = (const int*)d_in[1];
    const float* emb          = (const float*)d_in[2];
    const float* A            = (const float*)d_in[3];
    const float* w_block      = (const float*)d_in[4];
    const float* b_block      = (const float*)d_in[5];
    const float* bn_gamma     = (const float*)d_in[6];
    const float* bn_beta      = (const float*)d_in[7];
    const float* res_w        = (const float*)d_in[8];
    const float* res_b        = (const float*)d_in[9];
    const float* res_bn_gamma = (const float*)d_in[10];
    const float* res_bn_beta  = (const float*)d_in[11];
    float* out = (float*)d_out;

    cudaFuncSetAttribute(gemm_fused, cudaFuncAttributeMaxDynamicSharedMemorySize,
                         FUSED_SMEM_BYTES);

    prep_kernel<<<25, 32>>>(hop, emb, A, b_block);
    cvt_resw_kernel<<<32, 256>>>(res_w);
    gbuild_kernel<<<dim3(33, 8), 256>>>(w_block);
    xprep_kernel<<<dim3(16, 8, 8), 256>>>(x);
    gemm_fused<<<1696, 256, FUSED_SMEM_BYTES>>>(res_b);
    stats_kernel<<<512, 128>>>(bn_gamma, bn_beta, res_bn_gamma, res_bn_beta);
    final_kernel<<<4096, 256>>>(out);
}

// round 15
// speedup vs baseline: 1.1103x; 1.0391x over previous
#include <cuda_runtime.h>
#include <cuda_fp16.h>
#include <math.h>
#include <stdint.h>

// Problem constants
// N=16, C=128, T=128, V=25, K=3, H=8, OC=256, C/H=16, OC/H=32
// x: (16,128,128,25)  out: (16,256,128,25)

#define TV 3200          // T*V
#define CTV 409600       // C*T*V

// ---- scratch (device globals; allocation-free) ----
__device__ float d_BnA[24 * 625];
__device__ float d_bsum[256];
__device__ __align__(16) __half d_res_preh[16 * 256 * 3200];   // [n][ch][t][w]
__device__ __align__(16) __half d_out_preh[16 * 256 * 3200];   // [n][ch][t][w]
__device__ __align__(16) __half d_G2h[8 * 896 * 400];   // fused weights, k=c*25+v
__device__ __align__(16) __half d_xrh[16 * 8 * 128 * 400]; // x for main GEMM
__device__ __align__(16) __half d_xth[16 * 3200 * 128];    // x for res GEMM
__device__ __align__(16) __half d_rwh[256 * 128];          // res_w fp16
__device__ float d_ss[1024];
__device__ float d_rpart[800 * 256];             // res-path BN partials
__device__ float d_mpart[8 * 7 * 16 * 128 * 2];  // main-path BN partials

__device__ __forceinline__ void mma_f16(float c[4], const uint32_t a[4],
                                        const uint32_t b[2]) {
    asm volatile(
        "mma.sync.aligned.m16n8k16.row.col.f32.f16.f16.f32 "
        "{%0,%1,%2,%3},{%4,%5,%6,%7},{%8,%9},{%0,%1,%2,%3};"
        : "+f"(c[0]), "+f"(c[1]), "+f"(c[2]), "+f"(c[3])
        : "r"(a[0]), "r"(a[1]), "r"(a[2]), "r"(a[3]), "r"(b[0]), "r"(b[1]));
}
__device__ __forceinline__ uint32_t s2u(const void* p) {
    return (uint32_t)__cvta_generic_to_shared(p);
}
#define LDSM4(r0, r1, r2, r3, addr)                                        \
    asm volatile("ldmatrix.sync.aligned.m8n8.x4.shared.b16 {%0,%1,%2,%3},[%4];" \
                 : "=r"(r0), "=r"(r1), "=r"(r2), "=r"(r3) : "r"(addr))
__device__ __forceinline__ void cp16(uint32_t dst, const void* src) {
    asm volatile("cp.async.cg.shared.global [%0], [%1], 16;"
                 :: "r"(dst), "l"(src));
}
#define CP_COMMIT() asm volatile("cp.async.commit_group;" ::: "memory")
#define CP_WAIT(n)  asm volatile("cp.async.wait_group %0;" :: "n"(n) : "memory")

// ---------------------------------------------------------------------------
// Kernel 1: build BnA and summed bias.
// ---------------------------------------------------------------------------
__global__ void prep_kernel(const int* __restrict__ hop,
                            const float* __restrict__ emb,
                            const float* __restrict__ A,
                            const float* __restrict__ b_block) {
    int g = blockIdx.x;
    int w = threadIdx.x;
    if (g < 24) {
        if (w < 25) {
            const float* eg = emb + g * 12;
            const float* Ag = A + g * 625;
            float sb = 0.f, sa = 0.f;
            for (int v = 0; v < 25; ++v) {
                float bv = eg[hop[v * 25 + w]];
                float av = Ag[v * 25 + w];
                sb += bv * bv;
                sa += av * av;
            }
            float rb = 1.f / (sqrtf(sb) + 1e-4f);
            float ra = 1.f / (sqrtf(sa) + 1e-4f);
            for (int v = 0; v < 25; ++v) {
                float bv = eg[hop[v * 25 + w]];
                float av = Ag[v * 25 + w];
                d_BnA[g * 625 + v * 25 + w] = bv * rb + av * ra;
            }
        }
    } else {
        for (int oc = w; oc < 256; oc += 32)
            d_bsum[oc] = b_block[oc] + b_block[256 + oc] + b_block[512 + oc];
    }
}

// ---------------------------------------------------------------------------
// Kernel 2 FUSED prep: blocks [0,1024) xprep, [1024,1288) gbuild,
// [1288,1320) cvt_resw. Dynamic smem union (26 KB).
// ---------------------------------------------------------------------------
#define PREP2_SMEM_BYTES (16 * 404 * 4)

__global__ __launch_bounds__(256) void prep2_kernel(
    const float* __restrict__ x,
    const float* __restrict__ w_block,
    const float* __restrict__ res_w) {
    extern __shared__ __align__(16) char sm[];
    const int bid = blockIdx.x;
    const int tid = threadIdx.x;

    if (bid < 1024) {
        // ---------------- xprep (r12 body) ----------------
        float* xs = (float*)sm;                 // [16][404]
        int n = bid & 15, h = (bid >> 4) & 7, tc = bid >> 7;
        const float* xb = x + n * CTV + h * 16 * TV + tc * 400;

#pragma unroll
        for (int it = 0; it < 7; ++it) {
            int idx = tid + it * 256;
            if (idx < 1600) {
                int c = idx / 100, f = idx - c * 100;
                *(float4*)(xs + c * 404 + f * 4) =
                    *(const float4*)(xb + c * TV + f * 4);
            }
        }
        __syncthreads();

        // d_xth[n][tv][h*16+c]
#pragma unroll
        for (int it = 0; it < 2; ++it) {
            int id = tid + it * 256;
            if (id < 400) {
                int tvp = id >> 1, q = id & 1;
                __half hA[8], hB[8];
#pragma unroll
                for (int cc = 0; cc < 8; ++cc) {
                    float2 v = *(const float2*)&xs[(q * 8 + cc) * 404 + tvp * 2];
                    hA[cc] = __float2half_rn(v.x);
                    hB[cc] = __float2half_rn(v.y);
                }
                __half* base = d_xth + (n * 3200 + tc * 400 + tvp * 2) * 128 +
                               h * 16 + q * 8;
                *(uint4*)base = *(uint4*)hA;
                *(uint4*)(base + 128) = *(uint4*)hB;
            }
        }
        // d_xrh[n][h][t][c*25+v]
        if (tid < 200) {
            int k0 = tid * 2;
            int c0 = k0 / 25, v0 = k0 - c0 * 25;
            int c1 = (v0 == 24) ? c0 + 1 : c0;
            int v1 = (v0 == 24) ? 0 : v0 + 1;
            const float* p0 = &xs[c0 * 404 + v0];
            const float* p1 = &xs[c1 * 404 + v1];
            __half2* dstr = (__half2*)(d_xrh + ((n * 8 + h) * 128 + tc * 16) * 400);
#pragma unroll
            for (int t = 0; t < 16; ++t)
                dstr[t * 200 + tid] = __floats2half2_rn(p0[t * 25], p1[t * 25]);
        }
    } else if (bid < 1288) {
        // ---------------- gbuild (r12 body) ----------------
        int id2 = bid - 1024;
        int o = id2 % 33;
        int h = id2 / 33;
        if (o == 32) {
            __half* dst = d_G2h + (h * 896 + 800) * 400;
            for (int idx = tid; idx < 96 * 400; idx += 256) dst[idx] = __half(0.f);
            return;
        }
        float* bna = (float*)sm;        // [1875]
        float* wg3 = bna + 1875;        // [48]
        for (int idx = tid; idx < 1875; idx += 256) {
            int k = idx / 625;
            bna[idx] = d_BnA[(k * 8 + h) * 625 + (idx - k * 625)];
        }
        if (tid < 48) {
            int k = tid / 16, c = tid & 15;
            wg3[tid] = w_block[(k * 8 + h) * 512 + o * 16 + c];
        }
        __syncthreads();
        __half* dst = d_G2h + (h * 896 + o * 25) * 400;
        for (int idx = tid; idx < 10000; idx += 256) {   // 25 w x 400 cv
            int w = idx / 400, cv = idx - w * 400;
            int c = cv / 25, v = cv - c * 25;
            int vw = v * 25 + w;
            float val = wg3[c] * bna[vw] + wg3[16 + c] * bna[625 + vw] +
                        wg3[32 + c] * bna[1250 + vw];
            dst[w * 400 + cv] = __float2half_rn(val);
        }
    } else {
        // ---------------- cvt_resw ----------------
        int idx = ((bid - 1288) * 256 + tid) * 4;
        float4 v = *(const float4*)(res_w + idx);
        __half2* dst = (__half2*)(d_rwh + idx);
        dst[0] = __floats2half2_rn(v.x, v.y);
        dst[1] = __floats2half2_rn(v.z, v.w);
    }
}

// ---------------------------------------------------------------------------
// Kernel 3 FUSED GEMMs (validated r14): bid < 896 main, else res.
// ---------------------------------------------------------------------------
#define FUSED_SMEM_BYTES (90112 + 2048)
#define BUFSZ 45056

__global__ __launch_bounds__(256, 2) void gemm_fused(
    const float* __restrict__ res_b) {
    extern __shared__ __align__(16) char smem[];
    float* part = (float*)(smem + 90112);

    const int tid = threadIdx.x;
    const int wid = tid >> 5, lane = tid & 31;
    const int gid = lane >> 2, tg = lane & 3;
    const int warp_m = wid >> 1;
    const int warp_n = wid & 1;
    const uint32_t smem_u = s2u(smem);
    const int r8 = (lane & 7);

    float c[2][8][4];
#pragma unroll
    for (int mt = 0; mt < 2; ++mt)
#pragma unroll
        for (int nt = 0; nt < 8; ++nt)
#pragma unroll
            for (int q = 0; q < 4; ++q) c[mt][nt][q] = 0.f;

    if (blockIdx.x < 896) {
        // ================= MAIN GEMM =================
        const int mid = blockIdx.x;
        const int n = mid & 15;
        const int mb = (mid >> 4) % 7;
        const int m0 = mb * 128;
        const int h = mid / 112;

        const __half* gbase = d_G2h + (h * 896 + m0) * 400;
        const __half* xbase = d_xrh + (n * 8 + h) * 128 * 400;

        uint32_t aAddr[2], bAddr[4];
#pragma unroll
        for (int mt = 0; mt < 2; ++mt) {
            int row = warp_m * 32 + mt * 16 + r8 + ((lane & 8) ? 8 : 0);
            aAddr[mt] = smem_u + row * 176 + ((lane & 16) ? 16 : 0);
        }
#pragma unroll
        for (int p = 0; p < 4; ++p) {
            int row = warp_n * 64 + p * 16 + r8 + ((lane & 16) ? 8 : 0);
            bAddr[p] = smem_u + 22528 + row * 176 + ((lane & 8) ? 16 : 0);
        }

        // issue chunk 0 into buffer 0
#pragma unroll
        for (int it = 0; it < 5; ++it) {
            int idx = tid + it * 256;
            int row = idx / 10, f = idx - row * 10;
            cp16(smem_u + row * 176 + f * 16, gbase + row * 400 + f * 8);
            cp16(smem_u + 22528 + row * 176 + f * 16, xbase + row * 400 + f * 8);
        }
        CP_COMMIT();

        for (int q = 0; q < 5; ++q) {
            const int buf = q & 1;
            if (q + 1 < 5) {
                const int nb = (q + 1) & 1;
                const int kc = (q + 1) * 80;
#pragma unroll
                for (int it = 0; it < 5; ++it) {
                    int idx = tid + it * 256;
                    int row = idx / 10, f = idx - row * 10;
                    cp16(smem_u + nb * BUFSZ + row * 176 + f * 16,
                         gbase + row * 400 + kc + f * 8);
                    cp16(smem_u + nb * BUFSZ + 22528 + row * 176 + f * 16,
                         xbase + row * 400 + kc + f * 8);
                }
                CP_COMMIT();
                CP_WAIT(1);
            } else {
                CP_WAIT(0);
            }
            __syncthreads();

            const uint32_t boff = buf * BUFSZ;
#pragma unroll
            for (int step = 0; step < 5; ++step) {
                uint32_t a[2][4], b[8][2];
#pragma unroll
                for (int mt = 0; mt < 2; ++mt)
                    LDSM4(a[mt][0], a[mt][1], a[mt][2], a[mt][3],
                          aAddr[mt] + boff + step * 32);
#pragma unroll
                for (int p = 0; p < 4; ++p) {
                    uint32_t r0, r1, r2, r3;
                    LDSM4(r0, r1, r2, r3, bAddr[p] + boff + step * 32);
                    b[2 * p][0] = r0;  b[2 * p][1] = r1;
                    b[2 * p + 1][0] = r2;  b[2 * p + 1][1] = r3;
                }
#pragma unroll
                for (int mt = 0; mt < 2; ++mt)
#pragma unroll
                    for (int nt = 0; nt < 8; ++nt)
                        mma_f16(c[mt][nt], a[mt], b[nt]);
            }
            __syncthreads();
        }

        // Epilogue
        __half* obase = d_out_preh + (n * 256 + h * 32) * TV;
#pragma unroll
        for (int mt = 0; mt < 2; ++mt) {
            int r0 = m0 + warp_m * 32 + mt * 16 + gid;
            int r1 = r0 + 8;
            int o0 = r0 / 25, o1 = r1 / 25;
            int w0 = r0 - o0 * 25, w1 = r1 - o1 * 25;
            float bias0 = (r0 < 800) ? d_bsum[h * 32 + o0] : 0.f;
            float bias1 = (r1 < 800) ? d_bsum[h * 32 + o1] : 0.f;
            float s0 = 0.f, q0 = 0.f, s1 = 0.f, q1 = 0.f;
            int colbase = warp_n * 64 + 2 * tg;
#pragma unroll
            for (int nt = 0; nt < 8; ++nt) {
                float v0 = c[mt][nt][0] + bias0;
                float v1 = c[mt][nt][1] + bias0;
                float v2 = c[mt][nt][2] + bias1;
                float v3 = c[mt][nt][3] + bias1;
                s0 += v0 + v1;  q0 += v0 * v0 + v1 * v1;
                s1 += v2 + v3;  q1 += v2 * v2 + v3 * v3;
                int col = colbase + nt * 8;
                if (r0 < 800) {
                    __half* d0 = obase + o0 * TV + col * 25 + w0;
                    d0[0] = __float2half_rn(v0);
                    d0[25] = __float2half_rn(v1);
                }
                if (r1 < 800) {
                    __half* d1 = obase + o1 * TV + col * 25 + w1;
                    d1[0] = __float2half_rn(v2);
                    d1[25] = __float2half_rn(v3);
                }
            }
#pragma unroll
            for (int off = 1; off <= 2; off <<= 1) {
                s0 += __shfl_xor_sync(0xFFFFFFFFu, s0, off);
                q0 += __shfl_xor_sync(0xFFFFFFFFu, q0, off);
                s1 += __shfl_xor_sync(0xFFFFFFFFu, s1, off);
                q1 += __shfl_xor_sync(0xFFFFFFFFu, q1, off);
            }
            if (tg == 0) {
                int r = warp_m * 32 + mt * 16 + gid;
                part[(warp_n * 128 + r) * 2] = s0;
                part[(warp_n * 128 + r) * 2 + 1] = q0;
                part[(warp_n * 128 + r + 8) * 2] = s1;
                part[(warp_n * 128 + r + 8) * 2 + 1] = q1;
            }
        }
        __syncthreads();
        if (tid < 128) {
            float s = part[tid * 2] + part[(128 + tid) * 2];
            float q = part[tid * 2 + 1] + part[(128 + tid) * 2 + 1];
            int blk = (h * 7 + mb) * 16 + n;
            d_mpart[(blk * 128 + tid) * 2] = s;
            d_mpart[(blk * 128 + tid) * 2 + 1] = q;
        }
    } else {
        // ================= RES GEMM =================
        const int rid = blockIdx.x - 896;
        const int tvb = rid % 25;
        const int ob = (rid / 25) & 1;
        const int n = rid / 50;
        const int tv0 = tvb * 128;
        const int o0 = ob * 128;

        {
            const uint4* srcA = (const uint4*)(d_rwh + o0 * 128);
            const uint4* srcB = (const uint4*)(d_xth + (n * 3200 + tv0) * 128);
#pragma unroll
            for (int it = 0; it < 8; ++it) {
                int idx = tid + it * 256;
                int row = idx >> 4, f = idx & 15;
                cp16(smem_u + row * 272 + f * 16, srcA + row * 16 + f);
                cp16(smem_u + 34816 + row * 272 + f * 16, srcB + row * 16 + f);
            }
            CP_COMMIT();
            CP_WAIT(0);
        }
        __syncthreads();

        uint32_t aAddr[2], bAddr[4];
#pragma unroll
        for (int mt = 0; mt < 2; ++mt) {
            int row = warp_m * 32 + mt * 16 + r8 + ((lane & 8) ? 8 : 0);
            aAddr[mt] = smem_u + row * 272 + ((lane & 16) ? 16 : 0);
        }
#pragma unroll
        for (int p = 0; p < 4; ++p) {
            int row = warp_n * 64 + p * 16 + r8 + ((lane & 16) ? 8 : 0);
            bAddr[p] = smem_u + 34816 + row * 272 + ((lane & 8) ? 16 : 0);
        }

#pragma unroll
        for (int step = 0; step < 8; ++step) {
            uint32_t a[2][4], b[8][2];
#pragma unroll
            for (int mt = 0; mt < 2; ++mt)
                LDSM4(a[mt][0], a[mt][1], a[mt][2], a[mt][3], aAddr[mt] + step * 32);
#pragma unroll
            for (int p = 0; p < 4; ++p) {
                uint32_t r0, r1, r2, r3;
                LDSM4(r0, r1, r2, r3, bAddr[p] + step * 32);
                b[2 * p][0] = r0;  b[2 * p][1] = r1;
                b[2 * p + 1][0] = r2;  b[2 * p + 1][1] = r3;
            }
#pragma unroll
            for (int mt = 0; mt < 2; ++mt)
#pragma unroll
                for (int nt = 0; nt < 8; ++nt)
                    mma_f16(c[mt][nt], a[mt], b[nt]);
        }

        const int colbase = tv0 + warp_n * 64 + 2 * tg;
#pragma unroll
        for (int mt = 0; mt < 2; ++mt) {
            int row0 = o0 + warp_m * 32 + mt * 16 + gid;
            float bias0 = res_b[row0];
            float bias1 = res_b[row0 + 8];
            float s0 = 0.f, q0 = 0.f, s1 = 0.f, q1 = 0.f;
            __half* dst0 = d_res_preh + (n * 256 + row0) * TV;
            __half* dst1 = dst0 + 8 * TV;
#pragma unroll
            for (int nt = 0; nt < 8; ++nt) {
                float v0 = c[mt][nt][0] + bias0;
                float v1 = c[mt][nt][1] + bias0;
                float v2 = c[mt][nt][2] + bias1;
                float v3 = c[mt][nt][3] + bias1;
                s0 += v0 + v1;  q0 += v0 * v0 + v1 * v1;
                s1 += v2 + v3;  q1 += v2 * v2 + v3 * v3;
                int col = colbase + nt * 8;
                *(__half2*)(dst0 + col) = __floats2half2_rn(v0, v1);
                *(__half2*)(dst1 + col) = __floats2half2_rn(v2, v3);
            }
#pragma unroll
            for (int off = 1; off <= 2; off <<= 1) {
                s0 += __shfl_xor_sync(0xFFFFFFFFu, s0, off);
                q0 += __shfl_xor_sync(0xFFFFFFFFu, q0, off);
                s1 += __shfl_xor_sync(0xFFFFFFFFu, s1, off);
                q1 += __shfl_xor_sync(0xFFFFFFFFu, q1, off);
            }
            if (tg == 0) {
                int r = warp_m * 32 + mt * 16 + gid;
                part[(warp_n * 128 + r) * 2] = s0;
                part[(warp_n * 128 + r) * 2 + 1] = q0;
                part[(warp_n * 128 + r + 8) * 2] = s1;
                part[(warp_n * 128 + r + 8) * 2 + 1] = q1;
            }
        }
        __syncthreads();
        if (tid < 128) {
            float s = part[tid * 2] + part[(128 + tid) * 2];
            float q = part[tid * 2 + 1] + part[(128 + tid) * 2 + 1];
            int blk = (n * 2 + ob) * 25 + tvb;
            d_rpart[blk * 256 + tid * 2] = s;
            d_rpart[blk * 256 + tid * 2 + 1] = q;
        }
    }
}

// ---------------------------------------------------------------------------
// Kernel 4: merged BN stats (both paths). Grid 512: which = blk>>8.
// ---------------------------------------------------------------------------
__global__ __launch_bounds__(128) void stats_kernel(
    const float* __restrict__ bn_gamma, const float* __restrict__ bn_beta,
    const float* __restrict__ res_bn_gamma, const float* __restrict__ res_bn_beta) {
    __shared__ float ssum[128];
    __shared__ float ssq[128];
    int which = blockIdx.x >> 8;
    int ch = blockIdx.x & 255;
    int tid = threadIdx.x;

    float s = 0.f, q = 0.f;
    if (which == 0) {
        int h = ch >> 5, o = ch & 31;
        for (int e = tid; e < 400; e += 128) {
            int w = e >> 4, nn = e & 15;
            int grow = o * 25 + w;
            int mb = grow >> 7, lr = grow & 127;
            int blk = (h * 7 + mb) * 16 + nn;
            s += d_mpart[(blk * 128 + lr) * 2];
            q += d_mpart[(blk * 128 + lr) * 2 + 1];
        }
    } else {
        int ob = ch >> 7, row = ch & 127;
        for (int e = tid; e < 400; e += 128) {
            int nn = e / 25, tvb = e - nn * 25;
            int blk = (nn * 2 + ob) * 25 + tvb;
            s += d_rpart[blk * 256 + row * 2];
            q += d_rpart[blk * 256 + row * 2 + 1];
        }
    }
    ssum[tid] = s;
    ssq[tid] = q;
    __syncthreads();
    for (int st = 64; st > 0; st >>= 1) {
        if (tid < st) {
            ssum[tid] += ssum[tid + st];
            ssq[tid] += ssq[tid + st];
        }
        __syncthreads();
    }
    if (tid == 0) {
        const float inv = 1.f / 51200.f;
        float mean = ssum[0] * inv;
        float var = ssq[0] * inv - mean * mean;
        float g = which ? res_bn_gamma[ch] : bn_gamma[ch];
        float b = which ? res_bn_beta[ch] : bn_beta[ch];
        float sc = g * rsqrtf(var + 1e-5f);
        d_ss[which * 512 + ch] = sc;
        d_ss[which * 512 + 256 + ch] = b - mean * sc;
    }
}

// ---------------------------------------------------------------------------
// Kernel 5: out = relu(BN(out_preh) + BN(res_preh)). Block per (n,ch).
// ---------------------------------------------------------------------------
__global__ __launch_bounds__(256) void final_kernel(float* __restrict__ out) {
    int b = blockIdx.x;                 // n*256 + ch
    int ch = b & 255;
    int tid = threadIdx.x;
    const uint2* po = (const uint2*)(d_out_preh + b * TV);
    const uint2* pr = (const uint2*)(d_res_preh + b * TV);
    float4* dst = (float4*)(out + b * TV);
    float so = d_ss[ch], ho = d_ss[256 + ch];
    float sr = d_ss[512 + ch], hr = d_ss[768 + ch];
#pragma unroll
    for (int it = 0; it < 4; ++it) {
        int idx = tid + it * 256;       // < 800 uint2 (4 halves each)
        if (idx < 800) {
            uint2 ov = po[idx];
            uint2 rv = pr[idx];
            float2 o0 = __half22float2(*(__half2*)&ov.x);
            float2 o1 = __half22float2(*(__half2*)&ov.y);
            float2 r0 = __half22float2(*(__half2*)&rv.x);
            float2 r1 = __half22float2(*(__half2*)&rv.y);
            float4 r;
            r.x = fmaxf(fmaf(o0.x, so, ho) + fmaf(r0.x, sr, hr), 0.f);
            r.y = fmaxf(fmaf(o0.y, so, ho) + fmaf(r0.y, sr, hr), 0.f);
            r.z = fmaxf(fmaf(o1.x, so, ho) + fmaf(r1.x, sr, hr), 0.f);
            r.w = fmaxf(fmaf(o1.y, so, ho) + fmaf(r1.y, sr, hr), 0.f);
            dst[idx] = r;
        }
    }
}

// ---------------------------------------------------------------------------
extern "C" void kernel_launch(void* const* d_in, const int* in_sizes, int n_in,
                              void* d_out, int out_size) {
    const float* x            = (const float*)d_in[0];
    const int*   hop          = (const int*)d_in[1];
    const float* emb          = (const float*)d_in[2];
    const float* A            = (const float*)d_in[3];
    const float* w_block      = (const float*)d_in[4];
    const float* b_block      = (const float*)d_in[5];
    const float* bn_gamma     = (const float*)d_in[6];
    const float* bn_beta      = (const float*)d_in[7];
    const float* res_w        = (const float*)d_in[8];
    const float* res_b        = (const float*)d_in[9];
    const float* res_bn_gamma = (const float*)d_in[10];
    const float* res_bn_beta  = (const float*)d_in[11];
    float* out = (float*)d_out;

    cudaFuncSetAttribute(gemm_fused, cudaFuncAttributeMaxDynamicSharedMemorySize,
                         FUSED_SMEM_BYTES);

    prep_kernel<<<25, 32>>>(hop, emb, A, b_block);
    prep2_kernel<<<1320, 256, PREP2_SMEM_BYTES>>>(x, w_block, res_w);
    gemm_fused<<<1696, 256, FUSED_SMEM_BYTES>>>(res_b);
    stats_kernel<<<512, 128>>>(bn_gamma, bn_beta, res_bn_gamma, res_bn_beta);
    final_kernel<<<4096, 256>>>(out);
}